// round 15
// baseline (speedup 1.0000x reference)
#include <cuda_runtime.h>
#include <cuda_pipeline_primitives.h>

#define B_N 16
#define K_N 20
#define H_N 256
#define W_N 256
#define HW_N 65536
#define RAD 4
#define STRIP_H 64
#define PADH 72      // STRIP_H + 2*RAD (divisible by 9)
#define NSTRIP 4
#define NPART (B_N*NSTRIP)   // 64 partials per class
#define KG 2                 // k's per stats block
#define CH 16                // HW chunks in stats
#define GR 9                 // rows per async group
#define NG (PADH/GR)         // 8 groups
#define SROWS (3*GR)         // 27-row smem ring (3 groups -> 1 barrier/group)
#define SW 264               // padded row width in smem

__device__ float g_stats4[B_N * K_N * CH * 4];
__device__ float g_num[K_N * NPART];
__device__ float g_den[K_N * NPART];

// ---------------------------------------------------------------------------
// Kernel 1: per-(b,k) partial sums over an HW chunk, KG=2, ALL 20 float4
// loads front-batched into registers (MLP=20/thread).
// ---------------------------------------------------------------------------
__global__ __launch_bounds__(256) void stats_kernel(const float* __restrict__ labels,
                                                    const float* __restrict__ inputs) {
    const int kt = blockIdx.x, b = blockIdx.y, ch = blockIdx.z, t = threadIdx.x;
    const int chunk = HW_N / CH;       // 4096 floats

    const float4* X0 = (const float4*)(inputs + (size_t)(b * 3 + 0) * HW_N + ch * chunk);
    const float4* X1 = (const float4*)(inputs + (size_t)(b * 3 + 1) * HW_N + ch * chunk);
    const float4* X2 = (const float4*)(inputs + (size_t)(b * 3 + 2) * HW_N + ch * chunk);
    const float4* L0 = (const float4*)(labels + (size_t)(b * K_N + kt * KG + 0) * HW_N + ch * chunk);
    const float4* L1 = (const float4*)(labels + (size_t)(b * K_N + kt * KG + 1) * HW_N + ch * chunk);

    // front-batch ALL loads: 4 iters x (2 labels + 3 inputs)
    float4 la[4], lb[4], x0[4], x1[4], x2[4];
    #pragma unroll
    for (int j = 0; j < 4; j++) {
        const int i = t + 256 * j;
        la[j] = __ldg(L0 + i);
        lb[j] = __ldg(L1 + i);
        x0[j] = __ldg(X0 + i);
        x1[j] = __ldg(X1 + i);
        x2[j] = __ldg(X2 + i);
    }

    float acc[2][4];
    #pragma unroll
    for (int kk = 0; kk < 2; kk++)
        #pragma unroll
        for (int j = 0; j < 4; j++) acc[kk][j] = 0.f;

    #pragma unroll
    for (int j = 0; j < 4; j++) {
        const float4 A = la[j], Bv = lb[j], v0 = x0[j], v1 = x1[j], v2 = x2[j];
        acc[0][0] += (A.x + A.y) + (A.z + A.w);
        acc[0][1] = fmaf(A.x, v0.x, fmaf(A.y, v0.y, fmaf(A.z, v0.z, fmaf(A.w, v0.w, acc[0][1]))));
        acc[0][2] = fmaf(A.x, v1.x, fmaf(A.y, v1.y, fmaf(A.z, v1.z, fmaf(A.w, v1.w, acc[0][2]))));
        acc[0][3] = fmaf(A.x, v2.x, fmaf(A.y, v2.y, fmaf(A.z, v2.z, fmaf(A.w, v2.w, acc[0][3]))));
        acc[1][0] += (Bv.x + Bv.y) + (Bv.z + Bv.w);
        acc[1][1] = fmaf(Bv.x, v0.x, fmaf(Bv.y, v0.y, fmaf(Bv.z, v0.z, fmaf(Bv.w, v0.w, acc[1][1]))));
        acc[1][2] = fmaf(Bv.x, v1.x, fmaf(Bv.y, v1.y, fmaf(Bv.z, v1.z, fmaf(Bv.w, v1.w, acc[1][2]))));
        acc[1][3] = fmaf(Bv.x, v2.x, fmaf(Bv.y, v2.y, fmaf(Bv.z, v2.z, fmaf(Bv.w, v2.w, acc[1][3]))));
    }

    #pragma unroll
    for (int kk = 0; kk < 2; kk++)
        #pragma unroll
        for (int j = 0; j < 4; j++)
            #pragma unroll
            for (int o = 16; o; o >>= 1)
                acc[kk][j] += __shfl_down_sync(0xffffffffu, acc[kk][j], o);

    __shared__ float red[8][8];
    const int wid = t >> 5, lane = t & 31;
    if (lane == 0) {
        #pragma unroll
        for (int kk = 0; kk < 2; kk++)
            #pragma unroll
            for (int j = 0; j < 4; j++) red[wid][kk * 4 + j] = acc[kk][j];
    }
    __syncthreads();
    if (t < 8) {
        float v = 0.f;
        #pragma unroll
        for (int w = 0; w < 8; w++) v += red[w][t];
        const int k = kt * KG + (t >> 2);
        g_stats4[((b * K_N + k) * CH + ch) * 4 + (t & 3)] = v;
    }
}

// ---------------------------------------------------------------------------
// Kernel 2: adjoint-fused main pass, cp.async staging, 3-group smem ring
// (single barrier per group).
//   num_k = sum (l*w) * blur(l),  den_k = sum w * blur(l)
// ---------------------------------------------------------------------------
__global__ __launch_bounds__(128) void main_kernel(const float* __restrict__ labels,
                                                   const float* __restrict__ inputs) {
    const int t = threadIdx.x;
    const int s = blockIdx.x;   // strip 0..3
    const int k = blockIdx.y;
    const int b = blockIdx.z;

    // g(d) = exp(-d^2 / (2*5^2)) -> literal immediates (FFMA-imm, rt=1)
    constexpr float G[9] = {0.72614903f, 0.83527021f, 0.92311635f, 0.98019867f, 1.0f,
                            0.98019867f, 0.92311635f, 0.83527021f, 0.72614903f};

    __shared__ float sTile[SROWS][SW];   // 27 x 264 floats = 28512 B
    __shared__ float sstat[4];

    if (t < 4) {
        float v = 0.f;
        #pragma unroll
        for (int ch = 0; ch < CH; ch++)
            v += g_stats4[((b * K_N + k) * CH + ch) * 4 + t];
        sstat[t] = v;
    }
    // zero the permanent horizontal pad columns (0..3 and 260..263)
    for (int z = t; z < SROWS * 8; z += 128) {
        const int r = z >> 3, c = z & 7;
        sTile[r][(c < 4) ? c : (SW - 8 + c)] = 0.f;
    }

    const float* lab = labels + (size_t)(b * K_N + k) * HW_N;
    const float* xp0 = inputs + (size_t)(b * 3) * HW_N;
    const float* xp1 = xp0 + HW_N;
    const float* xp2 = xp1 + HW_N;

    const int row0 = s * STRIP_H - RAD;   // global row of padded row 0
    const int oc0 = 2 * t;                // this thread's two output columns

    // --- stage one 9-row group: 9 rows x 64 float4 chunks ---
    auto stage = [&](int g) {
        #pragma unroll
        for (int task = t; task < GR * 64; task += 128) {
            const int r  = task >> 6;
            const int c4 = task & 63;
            const int pr = g * GR + r;
            const int gr = row0 + pr;
            float* dst = &sTile[pr % SROWS][4 + c4 * 4];
            if ((unsigned)gr < (unsigned)H_N) {
                __pipeline_memcpy_async(dst, lab + gr * W_N + c4 * 4, 16);
            } else {
                *(float4*)dst = make_float4(0.f, 0.f, 0.f, 0.f);
            }
        }
    };

    stage(0); __pipeline_commit();
    stage(1); __pipeline_commit();

    __syncthreads();   // sstat + pad zeros visible to all
    const float inv = 1.0f / (sstat[0] + 0.65536f);
    const float cm0 = sstat[1] * inv, cm1 = sstat[2] * inv, cm2 = sstat[3] * inv;

    float rb0[9], rb1[9];   // ring: h-blurred labels
    float ra0[9], ra1[9];   // ring: raw center labels
    float numAcc = 0.f, denAcc = 0.f;

    for (int g = 0; g < NG; g++) {
        __pipeline_wait_prior(1);
        __syncthreads();          // group g resident; group g-1 reads done
        // stage g+2 overwrites slot of group g-1 (3-ring) -> safe after barrier
        if (g + 2 < NG) { stage(g + 2); }
        __pipeline_commit();

        #pragma unroll
        for (int u = 0; u < 9; u++) {
            const int pr = g * GR + u;
            const float* srow = &sTile[pr % SROWS][oc0];  // pad col oc0 = global col oc0-4

            // --- 10-value horizontal window: 5 float2 LDS ---
            float v[10];
            #pragma unroll
            for (int i = 0; i < 5; i++) {
                const float2 a = *(const float2*)(srow + 2 * i);
                v[2 * i] = a.x; v[2 * i + 1] = a.y;
            }

            // --- horizontal 9-tap ---
            float h0 = v[0] * G[0], h1 = v[1] * G[0];
            #pragma unroll
            for (int j = 1; j < 9; j++) {
                h0 = fmaf(v[j],     G[j], h0);
                h1 = fmaf(v[j + 1], G[j], h1);
            }
            rb0[u] = h0; rb1[u] = h1;          // slot pr%9 == u
            ra0[u] = v[4]; ra1[u] = v[5];      // raw labels at own cols

            // --- vertical 9-tap completes output row gor = s*64 + pr - 8 ---
            if (pr >= 8) {
                float B0 = 0.f, B1 = 0.f;
                #pragma unroll
                for (int j = 0; j < 9; j++) {
                    const int slot = (u + 1 + j) % 9;   // (pr-8+j)%9, static
                    B0 = fmaf(rb0[slot], G[j], B0);
                    B1 = fmaf(rb1[slot], G[j], B1);
                }
                const int cs = (u + 5) % 9;             // slot of center row (pr-4)
                const float l0 = ra0[cs], l1 = ra1[cs];

                const int gor = s * STRIP_H + pr - 8;
                const int idx = gor * W_N + oc0;
                const float2 x0 = __ldg((const float2*)(xp0 + idx));
                const float2 x1 = __ldg((const float2*)(xp1 + idx));
                const float2 x2 = __ldg((const float2*)(xp2 + idx));

                const float a0 = x0.x - cm0, a1 = x1.x - cm1, a2 = x2.x - cm2;
                const float d0 = fmaf(a0, a0, fmaf(a1, a1, a2 * a2));
                const float c0 = x0.y - cm0, c1 = x1.y - cm1, c2 = x2.y - cm2;
                const float d1 = fmaf(c0, c0, fmaf(c1, c1, c2 * c2));
                const float w0 = __expf(-d0 * d0);
                const float w1 = __expf(-d1 * d1);

                numAcc = fmaf(l0 * w0, B0, numAcc);
                numAcc = fmaf(l1 * w1, B1, numAcc);
                denAcc = fmaf(w0, B0, denAcc);
                denAcc = fmaf(w1, B1, denAcc);
            }
        }
    }

    // --- deterministic block reduction ---
    #pragma unroll
    for (int o = 16; o; o >>= 1) {
        numAcc += __shfl_down_sync(0xffffffffu, numAcc, o);
        denAcc += __shfl_down_sync(0xffffffffu, denAcc, o);
    }
    __shared__ float rn[4], rd[4];
    if ((t & 31) == 0) { rn[t >> 5] = numAcc; rd[t >> 5] = denAcc; }
    __syncthreads();
    if (t == 0) {
        const float n = (rn[0] + rn[1]) + (rn[2] + rn[3]);
        const float d = (rd[0] + rd[1]) + (rd[2] + rd[3]);
        const int idx = (k * B_N + b) * NSTRIP + s;
        g_num[idx] = n;
        g_den[idx] = d;
    }
}

// ---------------------------------------------------------------------------
// Kernel 3: final deterministic reduction -> scalar loss
// ---------------------------------------------------------------------------
__global__ void finish_kernel(float* __restrict__ out) {
    __shared__ float sv[K_N];
    const int t = threadIdx.x;
    if (t < K_N) {
        float n = 0.f, d = 0.f;
        for (int i = 0; i < NPART; i++) {
            n += g_num[t * NPART + i];
            d += g_den[t * NPART + i];
        }
        sv[t] = fabsf(n / (d + 1e-6f));
    }
    __syncthreads();
    if (t == 0) {
        float loss = 0.f;
        for (int i = 0; i < K_N; i++) loss += sv[i];
        out[0] = (float)K_N - loss;
    }
}

// ---------------------------------------------------------------------------
extern "C" void kernel_launch(void* const* d_in, const int* in_sizes, int n_in,
                              void* d_out, int out_size) {
    (void)n_in; (void)out_size;
    const float* labels;
    const float* inputs;
    if (in_sizes[0] == B_N * K_N * HW_N) {
        labels = (const float*)d_in[0];
        inputs = (const float*)d_in[1];
    } else {
        labels = (const float*)d_in[1];
        inputs = (const float*)d_in[0];
    }
    float* out = (float*)d_out;

    stats_kernel<<<dim3(K_N / KG, B_N, CH), 256>>>(labels, inputs);
    main_kernel<<<dim3(NSTRIP, K_N, B_N), 128>>>(labels, inputs);
    finish_kernel<<<1, 32>>>(out);
}

// round 16
// speedup vs baseline: 1.1935x; 1.1935x over previous
#include <cuda_runtime.h>
#include <cuda_pipeline_primitives.h>

#define B_N 16
#define K_N 20
#define H_N 256
#define W_N 256
#define HW_N 65536
#define RAD 4
#define STRIP_H 64
#define PADH 72      // STRIP_H + 2*RAD (divisible by 9)
#define NSTRIP 4
#define NPART (B_N*NSTRIP)   // 64 partials per class
#define KG 2                 // k's per stats block
#define CH 16                // HW chunks in stats
#define GR 9                 // rows per async group
#define NG (PADH/GR)         // 8 groups
#define SROWS (2*GR)         // 18-row smem ring (2 groups)
#define SW 264               // padded row width in smem

__device__ float g_stats4[B_N * K_N * CH * 4];
__device__ float g_num[K_N * NPART];
__device__ float g_den[K_N * NPART];

// ---------------------------------------------------------------------------
// Kernel 1: per-(b,k) partial sums over an HW chunk (R7 version, 22 us).
// ---------------------------------------------------------------------------
__global__ __launch_bounds__(256) void stats_kernel(const float* __restrict__ labels,
                                                    const float* __restrict__ inputs) {
    const int kt = blockIdx.x, b = blockIdx.y, ch = blockIdx.z, t = threadIdx.x;
    const int chunk = HW_N / CH;       // 4096 floats
    const int nf4 = chunk / 4;         // 1024 float4

    const float4* X0 = (const float4*)(inputs + (size_t)(b * 3 + 0) * HW_N + ch * chunk);
    const float4* X1 = (const float4*)(inputs + (size_t)(b * 3 + 1) * HW_N + ch * chunk);
    const float4* X2 = (const float4*)(inputs + (size_t)(b * 3 + 2) * HW_N + ch * chunk);
    const float4* L[KG];
    #pragma unroll
    for (int kk = 0; kk < KG; kk++)
        L[kk] = (const float4*)(labels + (size_t)(b * K_N + kt * KG + kk) * HW_N + ch * chunk);

    float acc[KG][4];
    #pragma unroll
    for (int kk = 0; kk < KG; kk++)
        #pragma unroll
        for (int j = 0; j < 4; j++) acc[kk][j] = 0.f;

    #pragma unroll 4
    for (int i = t; i < nf4; i += 256) {
        const float4 x0 = X0[i], x1 = X1[i], x2 = X2[i];
        #pragma unroll
        for (int kk = 0; kk < KG; kk++) {
            const float4 l = L[kk][i];
            acc[kk][0] += (l.x + l.y) + (l.z + l.w);
            acc[kk][1] = fmaf(l.x, x0.x, fmaf(l.y, x0.y, fmaf(l.z, x0.z, fmaf(l.w, x0.w, acc[kk][1]))));
            acc[kk][2] = fmaf(l.x, x1.x, fmaf(l.y, x1.y, fmaf(l.z, x1.z, fmaf(l.w, x1.w, acc[kk][2]))));
            acc[kk][3] = fmaf(l.x, x2.x, fmaf(l.y, x2.y, fmaf(l.z, x2.z, fmaf(l.w, x2.w, acc[kk][3]))));
        }
    }

    #pragma unroll
    for (int kk = 0; kk < KG; kk++)
        #pragma unroll
        for (int j = 0; j < 4; j++)
            #pragma unroll
            for (int o = 16; o; o >>= 1)
                acc[kk][j] += __shfl_down_sync(0xffffffffu, acc[kk][j], o);

    __shared__ float red[8][KG * 4];
    const int wid = t >> 5, lane = t & 31;
    if (lane == 0) {
        #pragma unroll
        for (int kk = 0; kk < KG; kk++)
            #pragma unroll
            for (int j = 0; j < 4; j++) red[wid][kk * 4 + j] = acc[kk][j];
    }
    __syncthreads();
    if (t < KG * 4) {
        float v = 0.f;
        #pragma unroll
        for (int w = 0; w < 8; w++) v += red[w][t];
        const int k = kt * KG + (t >> 2);
        g_stats4[((b * K_N + k) * CH + ch) * 4 + (t & 3)] = v;
    }
}

// ---------------------------------------------------------------------------
// Kernel 2: adjoint-fused main pass (R7 dataflow: 18-row ring, 2 barriers per
// group, stage AFTER compute). Group 0 peeled; x-loads hoisted above h-blur.
//   num_k = sum (l*w) * blur(l),  den_k = sum w * blur(l)
// ---------------------------------------------------------------------------
__global__ __launch_bounds__(128) void main_kernel(const float* __restrict__ labels,
                                                   const float* __restrict__ inputs) {
    const int t = threadIdx.x;
    const int s = blockIdx.x;   // strip 0..3
    const int k = blockIdx.y;
    const int b = blockIdx.z;

    // g(d) = exp(-d^2 / (2*5^2)) -> literal immediates (FFMA-imm, rt=1)
    constexpr float G[9] = {0.72614903f, 0.83527021f, 0.92311635f, 0.98019867f, 1.0f,
                            0.98019867f, 0.92311635f, 0.83527021f, 0.72614903f};

    __shared__ float sTile[SROWS][SW];   // 18 x 264 floats
    __shared__ float sstat[4];

    if (t < 4) {
        float v = 0.f;
        #pragma unroll
        for (int ch = 0; ch < CH; ch++)
            v += g_stats4[((b * K_N + k) * CH + ch) * 4 + t];
        sstat[t] = v;
    }
    // zero the permanent horizontal pad columns (0..3 and 260..263)
    for (int z = t; z < SROWS * 8; z += 128) {
        const int r = z >> 3, c = z & 7;
        sTile[r][(c < 4) ? c : (SW - 8 + c)] = 0.f;
    }

    const float* lab = labels + (size_t)(b * K_N + k) * HW_N;
    const float* xp0 = inputs + (size_t)(b * 3) * HW_N;
    const float* xp1 = xp0 + HW_N;
    const float* xp2 = xp1 + HW_N;

    const int row0 = s * STRIP_H - RAD;   // global row of padded row 0
    const int oc0 = 2 * t;                // this thread's two output columns

    // --- stage one 9-row group: 9 rows x 64 float4 chunks ---
    auto stage = [&](int g) {
        #pragma unroll
        for (int task = t; task < GR * 64; task += 128) {
            const int r  = task >> 6;
            const int c4 = task & 63;
            const int pr = g * GR + r;
            const int gr = row0 + pr;
            float* dst = &sTile[pr % SROWS][4 + c4 * 4];
            if ((unsigned)gr < (unsigned)H_N) {
                __pipeline_memcpy_async(dst, lab + gr * W_N + c4 * 4, 16);
            } else {
                *(float4*)dst = make_float4(0.f, 0.f, 0.f, 0.f);
            }
        }
    };

    stage(0); __pipeline_commit();
    stage(1); __pipeline_commit();

    float rb0[9], rb1[9];   // ring: h-blurred labels
    float ra0[9], ra1[9];   // ring: raw center labels
    float numAcc = 0.f, denAcc = 0.f;
    float cm0, cm1, cm2;

    // h-blur of one staged row into ring slot u
    #define HBLUR(u, pr) do {                                              \
        const float* srow = &sTile[(pr) % SROWS][oc0];                     \
        float v[10];                                                       \
        _Pragma("unroll")                                                  \
        for (int i = 0; i < 5; i++) {                                      \
            const float2 a = *(const float2*)(srow + 2 * i);               \
            v[2 * i] = a.x; v[2 * i + 1] = a.y;                            \
        }                                                                  \
        float h0 = v[0] * G[0], h1 = v[1] * G[0];                          \
        _Pragma("unroll")                                                  \
        for (int j = 1; j < 9; j++) {                                      \
            h0 = fmaf(v[j],     G[j], h0);                                 \
            h1 = fmaf(v[j + 1], G[j], h1);                                 \
        }                                                                  \
        rb0[u] = h0; rb1[u] = h1;                                          \
        ra0[u] = v[4]; ra1[u] = v[5];                                      \
    } while (0)

    // v-blur + weights + accumulate for output row (pr-8); x loads already done
    #define VOUT(u, gor, x0, x1, x2) do {                                  \
        float B0 = 0.f, B1 = 0.f;                                          \
        _Pragma("unroll")                                                  \
        for (int j = 0; j < 9; j++) {                                      \
            const int slot = ((u) + 1 + j) % 9;                            \
            B0 = fmaf(rb0[slot], G[j], B0);                                \
            B1 = fmaf(rb1[slot], G[j], B1);                                \
        }                                                                  \
        const int cs = ((u) + 5) % 9;                                      \
        const float l0 = ra0[cs], l1 = ra1[cs];                            \
        const float a0 = x0.x - cm0, a1 = x1.x - cm1, a2 = x2.x - cm2;     \
        const float d0 = fmaf(a0, a0, fmaf(a1, a1, a2 * a2));              \
        const float c0 = x0.y - cm0, c1 = x1.y - cm1, c2 = x2.y - cm2;     \
        const float d1 = fmaf(c0, c0, fmaf(c1, c1, c2 * c2));              \
        const float w0 = __expf(-d0 * d0);                                 \
        const float w1 = __expf(-d1 * d1);                                 \
        numAcc = fmaf(l0 * w0, B0, numAcc);                                \
        numAcc = fmaf(l1 * w1, B1, numAcc);                                \
        denAcc = fmaf(w0, B0, denAcc);                                     \
        denAcc = fmaf(w1, B1, denAcc);                                     \
    } while (0)

    // ---- group 0 (peeled): rows 0..8, output only at u==8 (gor=0) ----
    {
        __pipeline_wait_prior(1);
        __syncthreads();          // group 0 resident; sstat + pads visible

        const float inv = 1.0f / (sstat[0] + 0.65536f);
        cm0 = sstat[1] * inv; cm1 = sstat[2] * inv; cm2 = sstat[3] * inv;

        #pragma unroll
        for (int u = 0; u < 8; u++) HBLUR(u, u);
        {
            const float2 x0 = __ldg((const float2*)(xp0 + s * STRIP_H * W_N + oc0));
            const float2 x1 = __ldg((const float2*)(xp1 + s * STRIP_H * W_N + oc0));
            const float2 x2 = __ldg((const float2*)(xp2 + s * STRIP_H * W_N + oc0));
            HBLUR(8, 8);
            VOUT(8, s * STRIP_H, x0, x1, x2);
        }

        __syncthreads();
        stage(2);
        __pipeline_commit();
    }

    // ---- groups 1..NG-1: every row produces an output row ----
    for (int g = 1; g < NG; g++) {
        __pipeline_wait_prior(1);
        __syncthreads();          // group g resident

        #pragma unroll
        for (int u = 0; u < 9; u++) {
            const int pr = g * GR + u;
            const int gor = s * STRIP_H + pr - 8;
            const int idx = gor * W_N + oc0;
            // hoisted output-row loads (independent of h-blur chain)
            const float2 x0 = __ldg((const float2*)(xp0 + idx));
            const float2 x1 = __ldg((const float2*)(xp1 + idx));
            const float2 x2 = __ldg((const float2*)(xp2 + idx));

            HBLUR(u, pr);
            VOUT(u, gor, x0, x1, x2);
        }

        __syncthreads();          // all threads done reading group g
        if (g + 2 < NG) { stage(g + 2); }
        __pipeline_commit();
    }

    #undef HBLUR
    #undef VOUT

    // --- deterministic block reduction ---
    #pragma unroll
    for (int o = 16; o; o >>= 1) {
        numAcc += __shfl_down_sync(0xffffffffu, numAcc, o);
        denAcc += __shfl_down_sync(0xffffffffu, denAcc, o);
    }
    __shared__ float rn[4], rd[4];
    if ((t & 31) == 0) { rn[t >> 5] = numAcc; rd[t >> 5] = denAcc; }
    __syncthreads();
    if (t == 0) {
        const float n = (rn[0] + rn[1]) + (rn[2] + rn[3]);
        const float d = (rd[0] + rd[1]) + (rd[2] + rd[3]);
        const int idx = (k * B_N + b) * NSTRIP + s;
        g_num[idx] = n;
        g_den[idx] = d;
    }
}

// ---------------------------------------------------------------------------
// Kernel 3: final deterministic reduction -> scalar loss
// ---------------------------------------------------------------------------
__global__ void finish_kernel(float* __restrict__ out) {
    __shared__ float sv[K_N];
    const int t = threadIdx.x;
    if (t < K_N) {
        float n = 0.f, d = 0.f;
        for (int i = 0; i < NPART; i++) {
            n += g_num[t * NPART + i];
            d += g_den[t * NPART + i];
        }
        sv[t] = fabsf(n / (d + 1e-6f));
    }
    __syncthreads();
    if (t == 0) {
        float loss = 0.f;
        for (int i = 0; i < K_N; i++) loss += sv[i];
        out[0] = (float)K_N - loss;
    }
}

// ---------------------------------------------------------------------------
extern "C" void kernel_launch(void* const* d_in, const int* in_sizes, int n_in,
                              void* d_out, int out_size) {
    (void)n_in; (void)out_size;
    const float* labels;
    const float* inputs;
    if (in_sizes[0] == B_N * K_N * HW_N) {
        labels = (const float*)d_in[0];
        inputs = (const float*)d_in[1];
    } else {
        labels = (const float*)d_in[1];
        inputs = (const float*)d_in[0];
    }
    float* out = (float*)d_out;

    stats_kernel<<<dim3(K_N / KG, B_N, CH), 256>>>(labels, inputs);
    main_kernel<<<dim3(NSTRIP, K_N, B_N), 128>>>(labels, inputs);
    finish_kernel<<<1, 32>>>(out);
}